// round 1
// baseline (speedup 1.0000x reference)
#include <cuda_runtime.h>
#include <math.h>

#define NN 100000
#define NE 1000000
#define NF 128
#define NH 64
#define NC 40

// ---------------- scratch (device globals; no allocation allowed) ----------
__device__ float g_inv[NN];      // 1/safe_norm per node
__device__ float g_rowsum[NN];   // L1 row sums of sim
__device__ float g_degA[NN];     // attention surviving out-degree
__device__ float g_degC[NN];     // gcn_norm degree (by dst)
__device__ float g_ws[NN];       // self-loop weight exp(lam)
__device__ float g_dis[NN];      // deg^-1/2
__device__ float g_sim[NE];
__device__ float g_a[NE];
__device__ float g_we1[NE];      // layer-0 edge weights (also mask for pass 2)
__device__ float g_we2[NE];
__device__ float g_hw[NN * NH];  // x @ W1
__device__ float g_h[NN * NH];   // relu(conv1)
__device__ float g_hw2[NN * NC]; // h @ W2

__device__ __forceinline__ float warp_sum(float v) {
#pragma unroll
    for (int o = 16; o; o >>= 1) v += __shfl_xor_sync(0xffffffffu, v, o);
    return v;
}
__device__ __forceinline__ float warp_max(float v) {
#pragma unroll
    for (int o = 16; o; o >>= 1) v = fmaxf(v, __shfl_xor_sync(0xffffffffu, v, o));
    return v;
}

// ---------------- node norms (+ zero accumulators for this pass) -----------
template <int F>
__global__ void k_node_norm(const float* __restrict__ X) {
    int g = blockIdx.x * blockDim.x + threadIdx.x;
    int node = g >> 5, lane = g & 31;
    if (node >= NN) return;
    if (lane == 0) { g_rowsum[node] = 0.f; g_degA[node] = 0.f; }
    float ss = 0.f;
#pragma unroll
    for (int k = lane; k < F; k += 32) {
        float v = X[(size_t)node * F + k];
        ss += v * v;
    }
    ss = warp_sum(ss);
    if (lane == 0) g_inv[node] = (ss == 0.f) ? 1.f : rsqrtf(ss);
}

// ---------------- edge cosine sim + threshold + rowsum ---------------------
template <int F, bool MASKED>
__global__ void k_edge_sim(const float* __restrict__ X,
                           const int* __restrict__ src, const int* __restrict__ dst) {
    int g = blockIdx.x * blockDim.x + threadIdx.x;
    int e = g >> 5, lane = g & 31;
    if (e >= NE) return;
    if (MASKED) {
        if (!(g_we1[e] > 0.f)) { if (lane == 0) g_sim[e] = 0.f; return; }
    }
    int s = src[e], d = dst[e];
    float p = 0.f;
    if (F == 128) {
        const float4* a = reinterpret_cast<const float4*>(X + (size_t)s * F) + lane;
        const float4* b = reinterpret_cast<const float4*>(X + (size_t)d * F) + lane;
        float4 av = *a, bv = *b;
        p = av.x * bv.x + av.y * bv.y + av.z * bv.z + av.w * bv.w;
    } else {
        const float2* a = reinterpret_cast<const float2*>(X + (size_t)s * F) + lane;
        const float2* b = reinterpret_cast<const float2*>(X + (size_t)d * F) + lane;
        float2 av = *a, bv = *b;
        p = av.x * bv.x + av.y * bv.y;
    }
    p = warp_sum(p);
    if (lane == 0) {
        float sim = p * g_inv[s] * g_inv[d];
        if (sim < 0.1f) sim = 0.f;
        g_sim[e] = sim;
        if (sim > 0.f) atomicAdd(&g_rowsum[s], sim);
    }
}

// ---------------- a = sim / rowsum[src] -------------------------------------
__global__ void k_edge_a(const int* __restrict__ src) {
    int e = blockIdx.x * blockDim.x + threadIdx.x;
    if (e >= NE) return;
    float rs = g_rowsum[src[e]];
    g_a[e] = g_sim[e] / (rs == 0.f ? 1.f : rs);
}

// ---------------- learnable drop + w_e + surviving degree ------------------
__global__ void k_edge_keep(const int* __restrict__ src, const int* __restrict__ rev,
                            const float* __restrict__ Wd, const float* __restrict__ bd,
                            float* __restrict__ we) {
    int e = blockIdx.x * blockDim.x + threadIdx.x;
    if (e >= NE) return;
    float a = g_a[e];
    float ar = g_a[rev[e]];
    float z = a * Wd[0] + ar * Wd[1] + bd[0];   // sigmoid(z)>0.5 <=> z>0
    if (z > 0.f && a > 0.f) {
        we[e] = expf(a);
        atomicAdd(&g_degA[src[e]], 1.f);
    } else {
        we[e] = 0.f;
    }
}

// ---------------- self-loop weight + init gcn degree ------------------------
__global__ void k_node_ws() {
    int i = blockIdx.x * blockDim.x + threadIdx.x;
    if (i >= NN) return;
    float lam = 1.f / (g_degA[i] + 1.f);
    float ws = expf(lam);
    g_ws[i] = ws;
    g_degC[i] = ws + 1.f;   // self-loop w_s + gcn's own fill=1 self loop
}

__global__ void k_edge_degC(const int* __restrict__ dst, const float* __restrict__ we) {
    int e = blockIdx.x * blockDim.x + threadIdx.x;
    if (e >= NE) return;
    float w = we[e];
    if (w != 0.f) atomicAdd(&g_degC[dst[e]], w);
}

__global__ void k_node_dis() {
    int i = blockIdx.x * blockDim.x + threadIdx.x;
    if (i >= NN) return;
    float d = g_degC[i];
    g_dis[i] = (d > 0.f) ? rsqrtf(d) : 0.f;
}

// ---------------- GEMM: Y[n,M] = X[n,K] @ W[K,M] ----------------------------
template <int K, int M>
__global__ void k_gemm(const float* __restrict__ X, const float* __restrict__ W,
                       float* __restrict__ Y) {
    __shared__ float Ws[K][M];
    __shared__ float xs[128][17];
    int tid = threadIdx.x;          // 128 threads
    for (int i = tid; i < K * M; i += 128) Ws[i / M][i % M] = W[i];
    int node = blockIdx.x * 128 + tid;
    float acc[M];
#pragma unroll
    for (int j = 0; j < M; j++) acc[j] = 0.f;
    __syncthreads();
    for (int kb = 0; kb < K; kb += 16) {
#pragma unroll
        for (int t = 0; t < 16; t++) {
            int idx = t * 128 + tid;
            int r = idx >> 4, c = idx & 15;
            int nd = blockIdx.x * 128 + r;
            xs[r][c] = (nd < NN) ? X[(size_t)nd * K + kb + c] : 0.f;
        }
        __syncthreads();
#pragma unroll
        for (int k = 0; k < 16; k++) {
            float xv = xs[tid][k];
#pragma unroll
            for (int j = 0; j < M; j += 4) {
                float4 w4 = *reinterpret_cast<const float4*>(&Ws[kb + k][j]);
                acc[j]     += xv * w4.x;
                acc[j + 1] += xv * w4.y;
                acc[j + 2] += xv * w4.z;
                acc[j + 3] += xv * w4.w;
            }
        }
        __syncthreads();
    }
    if (node < NN) {
#pragma unroll
        for (int j = 0; j < M; j += 4)
            *reinterpret_cast<float4*>(&Y[(size_t)node * M + j]) =
                make_float4(acc[j], acc[j + 1], acc[j + 2], acc[j + 3]);
    }
}

// ---------------- self-loop term: out = dis^2*(ws+1)*hw ---------------------
template <int M>
__global__ void k_self_init(const float* __restrict__ hw, float* __restrict__ out) {
    size_t t = (size_t)blockIdx.x * blockDim.x + threadIdx.x;
    if (t >= (size_t)NN * M) return;
    int i = (int)(t / M);
    float dis = g_dis[i];
    out[t] = dis * dis * (g_ws[i] + 1.f) * hw[t];
}

// ---------------- edge aggregation (scatter-add) -----------------------------
template <int M>
__global__ void k_edge_agg(const int* __restrict__ src, const int* __restrict__ dst,
                           const float* __restrict__ we, const float* __restrict__ hw,
                           float* __restrict__ out) {
    int g = blockIdx.x * blockDim.x + threadIdx.x;
    int e = g >> 5, lane = g & 31;
    if (e >= NE) return;
    float w = we[e];
    if (w == 0.f) return;
    int s = src[e], d = dst[e];
    float coef = g_dis[s] * w * g_dis[d];
    const float* hs = hw + (size_t)s * M;
    float* od = out + (size_t)d * M;
#pragma unroll
    for (int c = lane; c < M; c += 32)
        atomicAdd(&od[c], coef * hs[c]);
}

__global__ void k_relu_bias(float* __restrict__ h, const float* __restrict__ b) {
    size_t t = (size_t)blockIdx.x * blockDim.x + threadIdx.x;
    if (t >= (size_t)NN * NH) return;
    h[t] = fmaxf(h[t] + b[t % NH], 0.f);
}

// ---------------- bias + log_softmax (warp per node, 40 classes) ------------
__global__ void k_lsm(float* __restrict__ out, const float* __restrict__ b) {
    int g = blockIdx.x * blockDim.x + threadIdx.x;
    int n = g >> 5, lane = g & 31;
    if (n >= NN) return;
    float* row = out + (size_t)n * NC;
    float v0 = row[lane] + b[lane];
    float v1 = -INFINITY;
    if (lane < NC - 32) v1 = row[lane + 32] + b[lane + 32];
    float m = warp_max(fmaxf(v0, v1));
    float s = expf(v0 - m) + ((lane < NC - 32) ? expf(v1 - m) : 0.f);
    s = warp_sum(s);
    float lse = logf(s);
    row[lane] = v0 - m - lse;
    if (lane < NC - 32) row[lane + 32] = v1 - m - lse;
}

// ---------------- host driver ------------------------------------------------
extern "C" void kernel_launch(void* const* d_in, const int* in_sizes, int n_in,
                              void* d_out, int out_size) {
    const float* x  = (const float*)d_in[0];
    const int* src  = (const int*)d_in[1];
    const int* dst  = (const int*)d_in[2];
    const int* rev  = (const int*)d_in[3];
    const float* W1 = (const float*)d_in[4];
    const float* b1 = (const float*)d_in[5];
    const float* W2 = (const float*)d_in[6];
    const float* b2 = (const float*)d_in[7];
    const float* Wd = (const float*)d_in[8];
    const float* bd = (const float*)d_in[9];
    float* out = (float*)d_out;

    float *p_hw, *p_h, *p_hw2, *p_we1, *p_we2;
    cudaGetSymbolAddress((void**)&p_hw,  g_hw);
    cudaGetSymbolAddress((void**)&p_h,   g_h);
    cudaGetSymbolAddress((void**)&p_hw2, g_hw2);
    cudaGetSymbolAddress((void**)&p_we1, g_we1);
    cudaGetSymbolAddress((void**)&p_we2, g_we2);

    const int TB = 256;
    int gb_node_warp = (NN * 32 + TB - 1) / TB;   // warp/node
    int gb_node      = (NN + TB - 1) / TB;        // thread/node
    int gb_edge      = (NE + TB - 1) / TB;        // thread/edge
    int gb_edge_warp = (NE * 32 + TB - 1) / TB;   // warp/edge
    int gb_gemm      = (NN + 127) / 128;

    // ===== layer 0 attention on x =====
    k_node_norm<NF><<<gb_node_warp, TB>>>(x);
    k_edge_sim<NF, false><<<gb_edge_warp, TB>>>(x, src, dst);
    k_edge_a<<<gb_edge, TB>>>(src);
    k_edge_keep<<<gb_edge, TB>>>(src, rev, Wd, bd, p_we1);
    k_node_ws<<<gb_node, TB>>>();
    k_edge_degC<<<gb_edge, TB>>>(dst, p_we1);
    k_node_dis<<<gb_node, TB>>>();

    // ===== conv 1: h = relu(gcn_conv(x, W1, b1)) =====
    k_gemm<NF, NH><<<gb_gemm, 128>>>(x, W1, p_hw);
    k_self_init<NH><<<(NN * NH + TB - 1) / TB, TB>>>(p_hw, p_h);
    k_edge_agg<NH><<<gb_edge_warp, TB>>>(src, dst, p_we1, p_hw, p_h);
    k_relu_bias<<<(NN * NH + TB - 1) / TB, TB>>>(p_h, b1);

    // ===== layer 1 attention on h (mask = w_e1 > 0) =====
    k_node_norm<NH><<<gb_node_warp, TB>>>(p_h);
    k_edge_sim<NH, true><<<gb_edge_warp, TB>>>(p_h, src, dst);
    k_edge_a<<<gb_edge, TB>>>(src);
    k_edge_keep<<<gb_edge, TB>>>(src, rev, Wd, bd, p_we2);
    k_node_ws<<<gb_node, TB>>>();
    k_edge_degC<<<gb_edge, TB>>>(dst, p_we2);
    k_node_dis<<<gb_node, TB>>>();

    // ===== conv 2 + log_softmax =====
    k_gemm<NH, NC><<<gb_gemm, 128>>>(p_h, W2, p_hw2);
    k_self_init<NC><<<(NN * NC + TB - 1) / TB, TB>>>(p_hw2, out);
    k_edge_agg<NC><<<gb_edge_warp, TB>>>(src, dst, p_we2, p_hw2, out);
    k_lsm<<<gb_node_warp, TB>>>(out, b2);
}

// round 2
// speedup vs baseline: 1.4275x; 1.4275x over previous
#include <cuda_runtime.h>
#include <math.h>

#define NN 100000
#define NE 1000000
#define EH 500000
#define NF 128
#define NH 64
#define NC 40

// ---------------- scratch (device globals; no allocation allowed) ----------
__device__ float g_inv[NN];      // 1/safe_norm per node
__device__ float g_rowsum[NN];   // L1 row sums of sim
__device__ float g_degA[NN];     // attention surviving out-degree
__device__ float g_degC[NN];     // gcn_norm degree accumulation (by dst)
__device__ float g_ws[NN];       // self-loop weight exp(lam)
__device__ float g_dis[NN];      // deg^-1/2
__device__ float g_sim[NE];
__device__ float g_we1[NE];      // layer-0 edge weights (also mask for pass 2)
__device__ float g_we2[NE];
__device__ float g_hw[NN * NH];  // x @ W1
__device__ float g_h[NN * NH];   // relu(conv1)
__device__ float g_hw2[NN * NC]; // h @ W2
// CSR by dst (topology only; built once per launch)
__device__ int g_cnt[NN];
__device__ int g_rowstart[NN];
__device__ int g_cursor[NN];
__device__ int g_eid[NE];
__device__ int g_bsum[128];
__device__ int g_boff[128];

__device__ __forceinline__ float warp_sum(float v) {
#pragma unroll
    for (int o = 16; o; o >>= 1) v += __shfl_xor_sync(0xffffffffu, v, o);
    return v;
}
__device__ __forceinline__ float warp_max(float v) {
#pragma unroll
    for (int o = 16; o; o >>= 1) v = fmaxf(v, __shfl_xor_sync(0xffffffffu, v, o));
    return v;
}

// ---------------- node norms (+ zero accumulators for this pass) -----------
template <int F, bool ZERO_CNT>
__global__ void k_node_norm(const float* __restrict__ X) {
    int g = blockIdx.x * blockDim.x + threadIdx.x;
    int node = g >> 5, lane = g & 31;
    if (node >= NN) return;
    if (lane == 0) { g_rowsum[node] = 0.f; g_degA[node] = 0.f; g_degC[node] = 0.f; }
    if (ZERO_CNT && lane == 1) g_cnt[node] = 0;
    float ss = 0.f;
#pragma unroll
    for (int k = lane; k < F; k += 32) {
        float v = X[(size_t)node * F + k];
        ss += v * v;
    }
    ss = warp_sum(ss);
    if (lane == 0) g_inv[node] = (ss == 0.f) ? 1.f : rsqrtf(ss);
}

// ---------------- CSR build (by dst) ----------------------------------------
__global__ void k_hist(const int* __restrict__ dst) {
    int e = blockIdx.x * blockDim.x + threadIdx.x;
    if (e < NE) atomicAdd(&g_cnt[dst[e]], 1);
}

__global__ void k_scan1() {  // 1024-wide block scans, exclusive within block
    int i = blockIdx.x * 1024 + threadIdx.x;
    int v = (i < NN) ? g_cnt[i] : 0;
    int lane = threadIdx.x & 31, wid = threadIdx.x >> 5;
    int x = v;
#pragma unroll
    for (int o = 1; o < 32; o <<= 1) {
        int t = __shfl_up_sync(0xffffffffu, x, o);
        if (lane >= o) x += t;
    }
    __shared__ int ws[32];
    if (lane == 31) ws[wid] = x;
    __syncthreads();
    if (wid == 0) {
        int y = ws[lane];
#pragma unroll
        for (int o = 1; o < 32; o <<= 1) {
            int t = __shfl_up_sync(0xffffffffu, y, o);
            if (lane >= o) y += t;
        }
        ws[lane] = y;
    }
    __syncthreads();
    int excl = x - v + (wid ? ws[wid - 1] : 0);
    if (i < NN) g_rowstart[i] = excl;
    if (threadIdx.x == 1023) g_bsum[blockIdx.x] = excl + v;  // block total
}

__global__ void k_scan2(int nb) {  // single block of 128: exclusive scan of block sums
    int t = threadIdx.x;
    int v = (t < nb) ? g_bsum[t] : 0;
    int lane = t & 31, wid = t >> 5;
    int x = v;
#pragma unroll
    for (int o = 1; o < 32; o <<= 1) {
        int u = __shfl_up_sync(0xffffffffu, x, o);
        if (lane >= o) x += u;
    }
    __shared__ int ws[4];
    if (lane == 31) ws[wid] = x;
    __syncthreads();
    int add = 0;
    for (int w = 0; w < wid; w++) add += ws[w];
    if (t < 128) g_boff[t] = x - v + add;
}

__global__ void k_scan3() {
    int i = blockIdx.x * blockDim.x + threadIdx.x;
    if (i >= NN) return;
    int rs = g_rowstart[i] + g_boff[i >> 10];
    g_rowstart[i] = rs;
    g_cursor[i] = rs;
}

__global__ void k_scatter(const int* __restrict__ dst) {
    int e = blockIdx.x * blockDim.x + threadIdx.x;
    if (e >= NE) return;
    int p = atomicAdd(&g_cursor[dst[e]], 1);
    g_eid[p] = e;
}

// ---------------- edge cosine sim (half edges, mirrored) + rowsum -----------
template <int F, bool MASKED>
__global__ void k_edge_sim(const float* __restrict__ X,
                           const int* __restrict__ src, const int* __restrict__ dst,
                           const int* __restrict__ rev) {
    int g = blockIdx.x * blockDim.x + threadIdx.x;
    int e = g >> 5, lane = g & 31;
    if (e >= EH) return;
    int e2 = rev[e];  // mirror edge (== e + EH for this dataset)
    bool m1 = true, m2 = true;
    if (MASKED) {
        m1 = g_we1[e] > 0.f;
        m2 = g_we1[e2] > 0.f;
        if (!(m1 || m2)) {
            if (lane == 0) { g_sim[e] = 0.f; g_sim[e2] = 0.f; }
            return;
        }
    }
    int s = src[e], d = dst[e];
    float p;
    if (F == 128) {
        float4 av = reinterpret_cast<const float4*>(X + (size_t)s * F)[lane];
        float4 bv = reinterpret_cast<const float4*>(X + (size_t)d * F)[lane];
        p = av.x * bv.x + av.y * bv.y + av.z * bv.z + av.w * bv.w;
    } else {
        float2 av = reinterpret_cast<const float2*>(X + (size_t)s * F)[lane];
        float2 bv = reinterpret_cast<const float2*>(X + (size_t)d * F)[lane];
        p = av.x * bv.x + av.y * bv.y;
    }
    p = warp_sum(p);
    if (lane == 0) {
        float raw = p * g_inv[s] * g_inv[d];
        if (raw < 0.1f) raw = 0.f;
        float s1 = m1 ? raw : 0.f;
        float s2 = m2 ? raw : 0.f;
        g_sim[e] = s1;
        g_sim[e2] = s2;
        if (s1 > 0.f) atomicAdd(&g_rowsum[s], s1);
        if (s2 > 0.f) atomicAdd(&g_rowsum[d], s2);
    }
}

// ------------- learnable drop + w_e + degA(src) + degC(dst) -----------------
__global__ void k_edge_keep(const int* __restrict__ src, const int* __restrict__ dst,
                            const int* __restrict__ rev,
                            const float* __restrict__ Wd, const float* __restrict__ bd,
                            float* __restrict__ we) {
    int e = blockIdx.x * blockDim.x + threadIdx.x;
    if (e >= NE) return;
    float sim = g_sim[e];
    if (!(sim > 0.f)) { we[e] = 0.f; return; }
    int s = src[e], d = dst[e];
    float rs = g_rowsum[s];
    float a = sim / (rs == 0.f ? 1.f : rs);
    float simr = g_sim[rev[e]];
    float rsr = g_rowsum[d];           // src of the reverse edge is d
    float ar = simr / (rsr == 0.f ? 1.f : rsr);
    float z = a * Wd[0] + ar * Wd[1] + bd[0];  // sigmoid(z)>0.5 <=> z>0
    if (z > 0.f) {
        float w = expf(a);
        we[e] = w;
        atomicAdd(&g_degA[s], 1.f);
        atomicAdd(&g_degC[d], w);
    } else {
        we[e] = 0.f;
    }
}

// ---------------- self-loop weight + gcn degree + dis ------------------------
__global__ void k_node_dis() {
    int i = blockIdx.x * blockDim.x + threadIdx.x;
    if (i >= NN) return;
    float lam = 1.f / (g_degA[i] + 1.f);
    float ws = expf(lam);
    g_ws[i] = ws;
    float deg = g_degC[i] + ws + 1.f;   // in-edges + attention self-loop + gcn fill=1
    g_dis[i] = rsqrtf(deg);
}

// ---------------- GEMM: Y[n,M] = X[n,K] @ W[K,M] ----------------------------
template <int K, int M>
__global__ void k_gemm(const float* __restrict__ X, const float* __restrict__ W,
                       float* __restrict__ Y) {
    __shared__ float Ws[K][M];
    __shared__ float xs[128][17];
    int tid = threadIdx.x;          // 128 threads
    for (int i = tid; i < K * M; i += 128) Ws[i / M][i % M] = W[i];
    int node = blockIdx.x * 128 + tid;
    float acc[M];
#pragma unroll
    for (int j = 0; j < M; j++) acc[j] = 0.f;
    __syncthreads();
    for (int kb = 0; kb < K; kb += 16) {
#pragma unroll
        for (int t = 0; t < 16; t++) {
            int idx = t * 128 + tid;
            int r = idx >> 4, c = idx & 15;
            int nd = blockIdx.x * 128 + r;
            xs[r][c] = (nd < NN) ? X[(size_t)nd * K + kb + c] : 0.f;
        }
        __syncthreads();
#pragma unroll
        for (int k = 0; k < 16; k++) {
            float xv = xs[tid][k];
#pragma unroll
            for (int j = 0; j < M; j += 4) {
                float4 w4 = *reinterpret_cast<const float4*>(&Ws[kb + k][j]);
                acc[j]     += xv * w4.x;
                acc[j + 1] += xv * w4.y;
                acc[j + 2] += xv * w4.z;
                acc[j + 3] += xv * w4.w;
            }
        }
        __syncthreads();
    }
    if (node < NN) {
#pragma unroll
        for (int j = 0; j < M; j += 4)
            *reinterpret_cast<float4*>(&Y[(size_t)node * M + j]) =
                make_float4(acc[j], acc[j + 1], acc[j + 2], acc[j + 3]);
    }
}

// -------- conv1 aggregation (CSR gather) + bias + relu, warp per node -------
__global__ void k_agg_h(const int* __restrict__ src, const float* __restrict__ we,
                        const float* __restrict__ b1) {
    int g = blockIdx.x * blockDim.x + threadIdx.x;
    int node = g >> 5, lane = g & 31;
    if (node >= NN) return;
    float dd = g_dis[node];
    float self = dd * (g_ws[node] + 1.f);
    float a0 = self * g_hw[(size_t)node * NH + lane];
    float a1 = self * g_hw[(size_t)node * NH + 32 + lane];
    int st = g_rowstart[node], cn = g_cnt[node];
    for (int i = 0; i < cn; i++) {
        int e = g_eid[st + i];
        float w = we[e];
        if (w != 0.f) {
            int s = src[e];
            float c = g_dis[s] * w;
            a0 += c * g_hw[(size_t)s * NH + lane];
            a1 += c * g_hw[(size_t)s * NH + 32 + lane];
        }
    }
    g_h[(size_t)node * NH + lane]      = fmaxf(dd * a0 + b1[lane], 0.f);
    g_h[(size_t)node * NH + 32 + lane] = fmaxf(dd * a1 + b1[lane + 32], 0.f);
}

// -------- conv2 aggregation + bias + log_softmax, warp per node -------------
__global__ void k_agg_out(const int* __restrict__ src, const float* __restrict__ we,
                          const float* __restrict__ b2, float* __restrict__ out) {
    int g = blockIdx.x * blockDim.x + threadIdx.x;
    int node = g >> 5, lane = g & 31;
    if (node >= NN) return;
    bool hi = lane < (NC - 32);
    float dd = g_dis[node];
    float self = dd * (g_ws[node] + 1.f);
    float a0 = self * g_hw2[(size_t)node * NC + lane];
    float a1 = hi ? self * g_hw2[(size_t)node * NC + 32 + lane] : 0.f;
    int st = g_rowstart[node], cn = g_cnt[node];
    for (int i = 0; i < cn; i++) {
        int e = g_eid[st + i];
        float w = we[e];
        if (w != 0.f) {
            int s = src[e];
            float c = g_dis[s] * w;
            a0 += c * g_hw2[(size_t)s * NC + lane];
            if (hi) a1 += c * g_hw2[(size_t)s * NC + 32 + lane];
        }
    }
    float v0 = dd * a0 + b2[lane];
    float v1 = hi ? (dd * a1 + b2[lane + 32]) : -INFINITY;
    float m = warp_max(fmaxf(v0, v1));
    float ssum = expf(v0 - m) + (hi ? expf(v1 - m) : 0.f);
    ssum = warp_sum(ssum);
    float lse = logf(ssum);
    out[(size_t)node * NC + lane] = v0 - m - lse;
    if (hi) out[(size_t)node * NC + 32 + lane] = v1 - m - lse;
}

// ---------------- host driver ------------------------------------------------
extern "C" void kernel_launch(void* const* d_in, const int* in_sizes, int n_in,
                              void* d_out, int out_size) {
    const float* x  = (const float*)d_in[0];
    const int* src  = (const int*)d_in[1];
    const int* dst  = (const int*)d_in[2];
    const int* rev  = (const int*)d_in[3];
    const float* W1 = (const float*)d_in[4];
    const float* b1 = (const float*)d_in[5];
    const float* W2 = (const float*)d_in[6];
    const float* b2 = (const float*)d_in[7];
    const float* Wd = (const float*)d_in[8];
    const float* bd = (const float*)d_in[9];
    float* out = (float*)d_out;

    float *p_hw, *p_h, *p_hw2, *p_we1, *p_we2;
    cudaGetSymbolAddress((void**)&p_hw,  g_hw);
    cudaGetSymbolAddress((void**)&p_h,   g_h);
    cudaGetSymbolAddress((void**)&p_hw2, g_hw2);
    cudaGetSymbolAddress((void**)&p_we1, g_we1);
    cudaGetSymbolAddress((void**)&p_we2, g_we2);

    const int TB = 256;
    int gb_node_warp = (NN * 32 + TB - 1) / TB;
    int gb_node      = (NN + TB - 1) / TB;
    int gb_edge      = (NE + TB - 1) / TB;
    int gb_ehalf_w   = (EH * 32 + TB - 1) / TB;
    int gb_gemm      = (NN + 127) / 128;
    int nb_scan      = (NN + 1023) / 1024;

    // ===== CSR build (topology only, shared by both convs) =====
    k_node_norm<NF, true><<<gb_node_warp, TB>>>(x);   // also zeros cnt/rowsum/degA/degC
    k_hist<<<gb_edge, TB>>>(dst);
    k_scan1<<<nb_scan, 1024>>>();
    k_scan2<<<1, 128>>>(nb_scan);
    k_scan3<<<gb_node, TB>>>();
    k_scatter<<<gb_edge, TB>>>(dst);

    // ===== layer 0 attention on x =====
    k_edge_sim<NF, false><<<gb_ehalf_w, TB>>>(x, src, dst, rev);
    k_edge_keep<<<gb_edge, TB>>>(src, dst, rev, Wd, bd, p_we1);
    k_node_dis<<<gb_node, TB>>>();

    // ===== conv 1: h = relu(gcn_conv(x, W1, b1)) =====
    k_gemm<NF, NH><<<gb_gemm, 128>>>(x, W1, p_hw);
    k_agg_h<<<gb_node_warp, TB>>>(src, p_we1, b1);

    // ===== layer 1 attention on h (mask = w_e1 > 0) =====
    k_node_norm<NH, false><<<gb_node_warp, TB>>>(p_h);
    k_edge_sim<NH, true><<<gb_ehalf_w, TB>>>(p_h, src, dst, rev);
    k_edge_keep<<<gb_edge, TB>>>(src, dst, rev, Wd, bd, p_we2);
    k_node_dis<<<gb_node, TB>>>();

    // ===== conv 2 + log_softmax =====
    k_gemm<NH, NC><<<gb_gemm, 128>>>(p_h, W2, p_hw2);
    k_agg_out<<<gb_node_warp, TB>>>(src, p_we2, b2, out);
}

// round 3
// speedup vs baseline: 1.9407x; 1.3595x over previous
#include <cuda_runtime.h>
#include <math.h>

#define NN 100000
#define NE 1000000
#define EH 500000
#define NF 128
#define NH 64
#define NC 40

// ---------------- scratch (device globals; no allocation allowed) ----------
__device__ float g_inv[NN];
__device__ float g_rowsum[NN];
__device__ float g_degA[NN];
__device__ float g_degC[NN];
__device__ float g_ws[NN];
__device__ float g_dis[NN];
__device__ float g_sim[NE];
__device__ float g_we1[NE];       // edge-order weights pass 1 (mask for pass 2)
__device__ float g_wecs[NE];      // CSR-ordered weights (rewritten per pass)
__device__ int   g_pos[NE];       // edge -> CSR slot
__device__ int   g_srccs[NE];     // CSR-ordered source node
__device__ float g_hw[NN * NH];
__device__ float g_h[NN * NH];
__device__ float g_hw2[NN * NC];
__device__ int g_cnt[NN];
__device__ int g_rowstart[NN];
__device__ int g_cursor[NN];
__device__ int g_bsum[128];

__device__ __forceinline__ float warp_red_sum(float v, int width) {
    for (int o = width >> 1; o; o >>= 1) v += __shfl_xor_sync(0xffffffffu, v, o);
    return v;
}
__device__ __forceinline__ float warp_red_max(float v, int width) {
    for (int o = width >> 1; o; o >>= 1) v = fmaxf(v, __shfl_xor_sync(0xffffffffu, v, o));
    return v;
}
__device__ __forceinline__ unsigned long long pack2(float lo, float hi) {
    unsigned long long r;
    asm("mov.b64 %0, {%1, %2};" : "=l"(r) : "f"(lo), "f"(hi));
    return r;
}
__device__ __forceinline__ void ffma2(unsigned long long& d, unsigned long long a,
                                      unsigned long long b) {
    asm("fma.rn.f32x2 %0, %1, %2, %0;" : "+l"(d) : "l"(a), "l"(b));
}
__device__ __forceinline__ float2 unpack2(unsigned long long v) {
    float2 r;
    asm("mov.b64 {%0, %1}, %2;" : "=f"(r.x), "=f"(r.y) : "l"(v));
    return r;
}

// ---------------- node norms on x (+ zero all accumulators) -----------------
__global__ void k_node_norm_x(const float* __restrict__ X) {
    int g = blockIdx.x * blockDim.x + threadIdx.x;
    int node = g >> 5, lane = g & 31;
    if (node >= NN) return;
    if (lane == 0) { g_rowsum[node] = 0.f; g_degA[node] = 0.f; g_degC[node] = 0.f; }
    if (lane == 1) g_cnt[node] = 0;
    float4 v = reinterpret_cast<const float4*>(X)[node * 32 + lane];
    float ss = v.x * v.x + v.y * v.y + v.z * v.z + v.w * v.w;
    ss = warp_red_sum(ss, 32);
    if (lane == 0) g_inv[node] = (ss == 0.f) ? 1.f : rsqrtf(ss);
}

// ---------------- CSR build (by dst) ----------------------------------------
__global__ void k_hist(const int* __restrict__ dst) {
    int e = blockIdx.x * blockDim.x + threadIdx.x;
    if (e < NE) atomicAdd(&g_cnt[dst[e]], 1);
}

__global__ void k_scan1() {
    int i = blockIdx.x * 1024 + threadIdx.x;
    int v = (i < NN) ? g_cnt[i] : 0;
    int lane = threadIdx.x & 31, wid = threadIdx.x >> 5;
    int x = v;
#pragma unroll
    for (int o = 1; o < 32; o <<= 1) {
        int t = __shfl_up_sync(0xffffffffu, x, o);
        if (lane >= o) x += t;
    }
    __shared__ int ws[32];
    if (lane == 31) ws[wid] = x;
    __syncthreads();
    if (wid == 0) {
        int y = ws[lane];
#pragma unroll
        for (int o = 1; o < 32; o <<= 1) {
            int t = __shfl_up_sync(0xffffffffu, y, o);
            if (lane >= o) y += t;
        }
        ws[lane] = y;
    }
    __syncthreads();
    int excl = x - v + (wid ? ws[wid - 1] : 0);
    if (i < NN) g_rowstart[i] = excl;
    if (threadIdx.x == 1023) g_bsum[blockIdx.x] = excl + v;
}

__global__ void k_scan3() {   // adds block-sum prefix inline (no scan2 kernel)
    __shared__ int s_off;
    int blk = blockIdx.x >> 2;   // 256*4 = 1024-chunk index
    if (threadIdx.x < 32) {
        int acc = 0;
        for (int j = threadIdx.x; j < blk; j += 32) acc += g_bsum[j];
#pragma unroll
        for (int o = 16; o; o >>= 1) acc += __shfl_xor_sync(0xffffffffu, acc, o);
        if (threadIdx.x == 0) s_off = acc;
    }
    __syncthreads();
    int i = blockIdx.x * 256 + threadIdx.x;
    if (i < NN) {
        int rs = g_rowstart[i] + s_off;
        g_rowstart[i] = rs;
        g_cursor[i] = rs;
    }
}

__global__ void k_scatter(const int* __restrict__ src, const int* __restrict__ dst) {
    int e = blockIdx.x * blockDim.x + threadIdx.x;
    if (e >= NE) return;
    int p = atomicAdd(&g_cursor[dst[e]], 1);
    g_pos[e] = p;
    g_srccs[p] = src[e];
}

// -------- edge cosine sim, one pair (e, e+EH) per L-lane group ---------------
template <int F, int L, bool MASKED>
__global__ void k_edge_sim(const float* __restrict__ X,
                           const int* __restrict__ src, const int* __restrict__ dst) {
    int g = blockIdx.x * blockDim.x + threadIdx.x;
    int e = g / L, lane = g % L;
    if (e >= EH) return;
    int e2 = e + EH;   // fixed reverse-edge layout from setup_inputs
    bool m1 = true, m2 = true;
    if (MASKED) { m1 = g_we1[e] > 0.f; m2 = g_we1[e2] > 0.f; }
    float p = 0.f;
    int s = 0, d = 0;
    if (m1 || m2) {
        s = src[e]; d = dst[e];
        float4 av = reinterpret_cast<const float4*>(X)[s * (F / 4) + lane];
        float4 bv = reinterpret_cast<const float4*>(X)[d * (F / 4) + lane];
        p = av.x * bv.x + av.y * bv.y + av.z * bv.z + av.w * bv.w;
    }
    p = warp_red_sum(p, L);
    if (lane == 0) {
        if (!(m1 || m2)) { g_sim[e] = 0.f; g_sim[e2] = 0.f; return; }
        float raw = p * g_inv[s] * g_inv[d];
        if (raw < 0.1f) raw = 0.f;
        float s1 = m1 ? raw : 0.f;
        float s2 = m2 ? raw : 0.f;
        g_sim[e] = s1;
        g_sim[e2] = s2;
        if (s1 > 0.f) atomicAdd(&g_rowsum[s], s1);
        if (s2 > 0.f) atomicAdd(&g_rowsum[d], s2);
    }
}

// ------- learnable drop for both directions of a pair; writes CSR weights ----
template <bool WRITE_EDGE>
__global__ void k_keep(const int* __restrict__ src, const int* __restrict__ dst,
                       const float* __restrict__ Wd, const float* __restrict__ bd,
                       float* __restrict__ we_edge) {
    int e = blockIdx.x * blockDim.x + threadIdx.x;
    if (e >= EH) return;
    int e2 = e + EH;
    float sf = g_sim[e], sb = g_sim[e2];
    int p1 = g_pos[e], p2 = g_pos[e2];
    if (!(sf > 0.f) && !(sb > 0.f)) {
        g_wecs[p1] = 0.f; g_wecs[p2] = 0.f;
        if (WRITE_EDGE) { we_edge[e] = 0.f; we_edge[e2] = 0.f; }
        return;
    }
    int s = src[e], d = dst[e];
    float rs = g_rowsum[s]; rs = (rs == 0.f) ? 1.f : rs;
    float rd = g_rowsum[d]; rd = (rd == 0.f) ? 1.f : rd;
    float af = sf / rs, ab = sb / rd;
    float w0 = Wd[0], w1 = Wd[1], bb = bd[0];
    float zf = af * w0 + ab * w1 + bb;
    float zb = ab * w0 + af * w1 + bb;
    float wf = 0.f, wb = 0.f;
    if (zf > 0.f && af > 0.f) {
        wf = expf(af);
        atomicAdd(&g_degA[s], 1.f);
        atomicAdd(&g_degC[d], wf);
    }
    if (zb > 0.f && ab > 0.f) {
        wb = expf(ab);
        atomicAdd(&g_degA[d], 1.f);
        atomicAdd(&g_degC[s], wb);
    }
    g_wecs[p1] = wf; g_wecs[p2] = wb;
    if (WRITE_EDGE) { we_edge[e] = wf; we_edge[e2] = wb; }
}

// -------- GEMM Y[n,M] = X[n,K] @ W[K,M] with packed f32x2 FMA (+fused dis) ---
template <int K, int M>
__global__ void k_gemm(const float* __restrict__ X, const float* __restrict__ W,
                       float* __restrict__ Y) {
    __shared__ float Ws[K][M];
    __shared__ float xs[128][17];
    int tid = threadIdx.x;
    int node = blockIdx.x * 128 + tid;
    if (node < NN) {   // fused node_dis for the current pass
        float lam = 1.f / (g_degA[node] + 1.f);
        float w = expf(lam);
        g_ws[node] = w;
        g_dis[node] = rsqrtf(g_degC[node] + w + 1.f);
    }
    for (int i = tid; i < K * M; i += 128) Ws[i / M][i % M] = W[i];
    unsigned long long acc[M / 2];
#pragma unroll
    for (int j = 0; j < M / 2; j++) acc[j] = 0ull;
    __syncthreads();
    for (int kb = 0; kb < K; kb += 16) {
#pragma unroll
        for (int t = 0; t < 16; t++) {
            int idx = t * 128 + tid;
            int r = idx >> 4, c = idx & 15;
            int nd = blockIdx.x * 128 + r;
            xs[r][c] = (nd < NN) ? X[(size_t)nd * K + kb + c] : 0.f;
        }
        __syncthreads();
#pragma unroll
        for (int k = 0; k < 16; k++) {
            float xv = xs[tid][k];
            unsigned long long x2 = pack2(xv, xv);
            const unsigned long long* wrow =
                reinterpret_cast<const unsigned long long*>(&Ws[kb + k][0]);
#pragma unroll
            for (int j = 0; j < M / 2; j++) ffma2(acc[j], wrow[j], x2);
        }
        __syncthreads();
    }
    if (node < NN) {
#pragma unroll
        for (int j = 0; j < M / 2; j += 2) {
            float2 lo = unpack2(acc[j]), hi = unpack2(acc[j + 1]);
            *reinterpret_cast<float4*>(&Y[(size_t)node * M + 2 * j]) =
                make_float4(lo.x, lo.y, hi.x, hi.y);
        }
    }
}

// ---- conv1 agg (CSR gather, half-warp/node, float4) + bias+relu + norm ------
__global__ void k_agg_h(const float* __restrict__ b1) {
    int g = blockIdx.x * blockDim.x + threadIdx.x;
    int node = g >> 4, lane = g & 15;
    if (node >= NN) return;
    const float4* hw4 = reinterpret_cast<const float4*>(g_hw);
    float dd = g_dis[node];
    float self = dd * (g_ws[node] + 1.f);
    float4 v = hw4[node * 16 + lane];
    float4 a = make_float4(self * v.x, self * v.y, self * v.z, self * v.w);
    int st = g_rowstart[node], cn = g_cnt[node];
    for (int i = 0; i < cn; i++) {
        float w = g_wecs[st + i];
        if (w != 0.f) {
            int s = g_srccs[st + i];
            float c = g_dis[s] * w;
            float4 u = hw4[s * 16 + lane];
            a.x += c * u.x; a.y += c * u.y; a.z += c * u.z; a.w += c * u.w;
        }
    }
    float4 b = reinterpret_cast<const float4*>(b1)[lane];
    float4 h;
    h.x = fmaxf(dd * a.x + b.x, 0.f);
    h.y = fmaxf(dd * a.y + b.y, 0.f);
    h.z = fmaxf(dd * a.z + b.z, 0.f);
    h.w = fmaxf(dd * a.w + b.w, 0.f);
    reinterpret_cast<float4*>(g_h)[node * 16 + lane] = h;
    float ss = h.x * h.x + h.y * h.y + h.z * h.z + h.w * h.w;
    __syncwarp();
    ss = warp_red_sum(ss, 16);
    if (lane == 0) {   // fused node_norm for pass 2 + accumulator re-zero
        g_inv[node] = (ss == 0.f) ? 1.f : rsqrtf(ss);
        g_rowsum[node] = 0.f; g_degA[node] = 0.f; g_degC[node] = 0.f;
    }
}

// ---- conv2 agg + bias + log_softmax (half-warp/node, lanes 0-9 x float4) ----
__global__ void k_agg_out(const float* __restrict__ b2, float* __restrict__ out) {
    int g = blockIdx.x * blockDim.x + threadIdx.x;
    int node = g >> 4, lane = g & 15;
    if (node >= NN) return;
    bool act = lane < (NC / 4);
    const float4* p4 = reinterpret_cast<const float4*>(g_hw2);
    float dd = g_dis[node];
    float self = dd * (g_ws[node] + 1.f);
    float4 a = make_float4(0.f, 0.f, 0.f, 0.f);
    if (act) {
        float4 v = p4[node * (NC / 4) + lane];
        a = make_float4(self * v.x, self * v.y, self * v.z, self * v.w);
    }
    int st = g_rowstart[node], cn = g_cnt[node];
    for (int i = 0; i < cn; i++) {
        float w = g_wecs[st + i];
        if (w != 0.f) {
            int s = g_srccs[st + i];
            float c = g_dis[s] * w;
            if (act) {
                float4 u = p4[s * (NC / 4) + lane];
                a.x += c * u.x; a.y += c * u.y; a.z += c * u.z; a.w += c * u.w;
            }
        }
    }
    float4 v4 = make_float4(0.f, 0.f, 0.f, 0.f);
    float mx = -INFINITY;
    if (act) {
        float4 b = reinterpret_cast<const float4*>(b2)[lane];
        v4.x = dd * a.x + b.x; v4.y = dd * a.y + b.y;
        v4.z = dd * a.z + b.z; v4.w = dd * a.w + b.w;
        mx = fmaxf(fmaxf(v4.x, v4.y), fmaxf(v4.z, v4.w));
    }
    __syncwarp();
    float m = warp_red_max(mx, 16);
    float es = 0.f;
    if (act)
        es = expf(v4.x - m) + expf(v4.y - m) + expf(v4.z - m) + expf(v4.w - m);
    es = warp_red_sum(es, 16);
    float lse = logf(es);
    if (act) {
        float4 r = make_float4(v4.x - m - lse, v4.y - m - lse,
                               v4.z - m - lse, v4.w - m - lse);
        *reinterpret_cast<float4*>(&out[(size_t)node * NC + 4 * lane]) = r;
    }
}

// ---------------- host driver ------------------------------------------------
extern "C" void kernel_launch(void* const* d_in, const int* in_sizes, int n_in,
                              void* d_out, int out_size) {
    const float* x  = (const float*)d_in[0];
    const int* src  = (const int*)d_in[1];
    const int* dst  = (const int*)d_in[2];
    const float* W1 = (const float*)d_in[4];
    const float* b1 = (const float*)d_in[5];
    const float* W2 = (const float*)d_in[6];
    const float* b2 = (const float*)d_in[7];
    const float* Wd = (const float*)d_in[8];
    const float* bd = (const float*)d_in[9];
    float* out = (float*)d_out;

    float *p_hw, *p_h, *p_hw2, *p_we1;
    cudaGetSymbolAddress((void**)&p_hw,  g_hw);
    cudaGetSymbolAddress((void**)&p_h,   g_h);
    cudaGetSymbolAddress((void**)&p_hw2, g_hw2);
    cudaGetSymbolAddress((void**)&p_we1, g_we1);

    const int TB = 256;
    int gb_node_warp = (NN * 32 + TB - 1) / TB;
    int gb_node_half = (NN * 16 + TB - 1) / TB;
    int gb_edge      = (NE + TB - 1) / TB;
    int gb_pair      = (EH + TB - 1) / TB;
    int gb_pair_w    = (EH * 32 + TB - 1) / TB;
    int gb_pair_h    = (EH * 16 + TB - 1) / TB;
    int gb_gemm      = (NN + 127) / 128;
    int nb_scan      = (NN + 1023) / 1024;

    // ===== CSR build + layer-0 attention =====
    k_node_norm_x<<<gb_node_warp, TB>>>(x);
    k_hist<<<gb_edge, TB>>>(dst);
    k_scan1<<<nb_scan, 1024>>>();
    k_scan3<<<(NN + 255) / 256, 256>>>();
    k_scatter<<<gb_edge, TB>>>(src, dst);
    k_edge_sim<NF, 32, false><<<gb_pair_w, TB>>>(x, src, dst);
    k_keep<true><<<gb_pair, TB>>>(src, dst, Wd, bd, p_we1);

    // ===== conv 1 =====
    k_gemm<NF, NH><<<gb_gemm, 128>>>(x, W1, p_hw);
    k_agg_h<<<gb_node_half, TB>>>(b1);

    // ===== layer-1 attention on h =====
    k_edge_sim<NH, 16, true><<<gb_pair_h, TB>>>(p_h, src, dst);
    k_keep<false><<<gb_pair, TB>>>(src, dst, Wd, bd, p_we1);

    // ===== conv 2 + log_softmax =====
    k_gemm<NH, NC><<<gb_gemm, 128>>>(p_h, W2, p_hw2);
    k_agg_out<<<gb_node_half, TB>>>(b2, out);
}